// round 14
// baseline (speedup 1.0000x reference)
#include <cuda_runtime.h>
#include <cstdint>

#define BATCH   4096
#define SEQ     32
#define DIM     256
#define VOCAB   50257
#define NALIVE  100
#define TOTAL4  51463168  // BATCH*VOCAB/4

// Scratch: compacted nonzero activations per row (empty in practice).
__device__ float g_val[BATCH * NALIVE];
__device__ int   g_idx[BATCH * NALIVE];
__device__ int   g_cnt[BATCH];

__device__ __forceinline__ float warp_sum(float v) {
    #pragma unroll
    for (int off = 16; off > 0; off >>= 1)
        v += __shfl_xor_sync(0xFFFFFFFFu, v, off);
    return v;
}
__device__ __forceinline__ float warp_max(float v) {
    #pragma unroll
    for (int off = 16; off > 0; off >>= 1)
        v = fmaxf(v, __shfl_xor_sync(0xFFFFFFFFu, v, off));
    return v;
}

// Named barrier for the 2 ctx warps only (fill warps never wait on it).
#define CTX_BAR() asm volatile("bar.sync 1, 64;" ::: "memory")

// Warp-specialized kernel: per block of 320 threads, warps 0-7 stream the
// zero-fill (identical to the proven fill loop) while warps 8-9 compute the
// ctx/RBF chain for row blockIdx.x. Ctx work rides inside storing blocks
// instead of displacing whole SM block-slots.
__global__ __launch_bounds__(320, 6)
void fused_fill_ctx_kernel(const int*   __restrict__ tok,
                           const float* __restrict__ te,
                           const float* __restrict__ pe,
                           const float* __restrict__ q,
                           const float* __restrict__ pos,
                           float*       __restrict__ out) {
    const int tid = threadIdx.x;
    const int b   = blockIdx.x;              // this block's ctx row

    if (tid < 256) {
        // ---------------- fill role: warps 0-7 ----------------
        const float4 z = make_float4(0.f, 0.f, 0.f, 0.f);
        float4* __restrict__ o4 = (float4*)out;
        const long stride = (long)BATCH * 256;
        for (long i = (long)b * 256 + tid; i < (long)TOTAL4; i += stride)
            __stcs(o4 + i, z);
        return;
    }

    // ---------------- ctx role: warps 8-9 (64 threads) ----------------
    __shared__ float s_emb[SEQ][DIM];        // 32 KB
    __shared__ float s_q[DIM];
    __shared__ float s_ctx[DIM];
    __shared__ float s_score[SEQ];
    __shared__ float s_w[SEQ];
    __shared__ float s_act[NALIVE];
    __shared__ int   s_tok[SEQ];

    const int t2   = tid - 256;              // 0..63
    const int lane = t2 & 31;
    const int w2   = t2 >> 5;                // 0..1

    #pragma unroll
    for (int i = 0; i < 4; i++) s_q[t2 + 64 * i] = q[t2 + 64 * i];
    if (t2 < SEQ) s_tok[t2] = tok[b * SEQ + t2];
    CTX_BAR();

    // Phase A: stage embeds (te read once). 2048 float4s over 64 threads.
    #pragma unroll 8
    for (int p = 0; p < 32; p++) {
        const int f  = p * 64 + t2;          // 0..2047
        const int s  = f >> 6;               // row 0..31
        const int c4 = f & 63;               // float4 within row
        const float4 t4 = __ldg((const float4*)(te + (size_t)s_tok[s] * DIM) + c4);
        const float4 p4 = __ldg((const float4*)(pe + s * DIM) + c4);
        float4 e;
        e.x = t4.x + p4.x; e.y = t4.y + p4.y;
        e.z = t4.z + p4.z; e.w = t4.w + p4.w;
        *((float4*)&s_emb[s][0] + c4) = e;
    }
    CTX_BAR();

    // Phase B: attention scores (warp w2 handles s = w2, w2+2, ...).
    for (int s = w2; s < SEQ; s += 2) {
        float p = 0.f;
        #pragma unroll
        for (int i = 0; i < 8; i++) {
            const int d = lane + 32 * i;
            p = fmaf(s_emb[s][d], s_q[d], p);
        }
        p = warp_sum(p);
        if (lane == 0) s_score[s] = p * (1.0f / 16.0f);   // / sqrt(256)
    }
    CTX_BAR();

    // Phase C: softmax over S=32 (ctx warp 0, one score per lane).
    if (w2 == 0) {
        const float sc = s_score[lane];
        const float m  = warp_max(sc);
        const float e  = expf(sc - m);
        const float s  = warp_sum(e);
        s_w[lane] = e / s;
    }
    CTX_BAR();

    // Phase D: context[d] = sum_s w[s] * embeds[s][d]  (4 dims per thread).
    #pragma unroll
    for (int i = 0; i < 4; i++) {
        const int d = t2 + 64 * i;
        float c = 0.f;
        #pragma unroll
        for (int s = 0; s < SEQ; s++) c = fmaf(s_w[s], s_emb[s][d], c);
        s_ctx[d] = c;
    }
    CTX_BAR();

    // Phase E: RBF distances (warp w2 handles j = w2, w2+2, ...).
    for (int j = w2; j < NALIVE; j += 2) {
        float p = 0.f;
        #pragma unroll
        for (int i = 0; i < 8; i++) {
            const int d = lane + 32 * i;
            const float df = s_ctx[d] - __ldg(pos + j * DIM + d);
            p = fmaf(df, df, p);
        }
        p = warp_sum(p);
        if (lane == 0) s_act[j] = expf(-2.0f * p);   // exp(-d2 / (2*0.5^2))
    }
    CTX_BAR();

    // Phase F: normalize + compact nonzeros (ctx warp 0).
    if (w2 == 0) {
        float sum = 0.f;
        for (int j = lane; j < NALIVE; j += 32) sum += s_act[j];
        sum = warp_sum(sum);
        const float denom = sum + 1e-8f;

        int cnt = 0;
        #pragma unroll
        for (int base = 0; base < 128; base += 32) {
            const int j = base + lane;
            float a = 0.f;
            bool nz = false;
            if (j < NALIVE) {
                a  = s_act[j] / denom;
                nz = (a != 0.0f);
            }
            const unsigned m = __ballot_sync(0xFFFFFFFFu, nz);
            const int pre = __popc(m & ((1u << lane) - 1u));
            if (nz) {
                g_val[b * NALIVE + cnt + pre] = a;
                g_idx[b * NALIVE + cnt + pre] = j;
            }
            cnt += __popc(m);
        }
        if (lane == 0) g_cnt[b] = cnt;
    }
}

// Sparse fixup: 16 blocks, each checks 256 rows IN PARALLEL (one load round),
// exits immediately when all counts are zero (the common case, ~4 us).
__global__ __launch_bounds__(256)
void fixup_kernel(const float* __restrict__ W, float* __restrict__ out) {
    __shared__ int   s_cnt_arr[256];
    __shared__ float s_val[NALIVE];
    __shared__ int   s_idx[NALIVE];

    const int tid = threadIdx.x;
    const int b0  = blockIdx.x * 256;

    const int mycnt = g_cnt[b0 + tid];
    s_cnt_arr[tid] = mycnt;
    if (__syncthreads_count(mycnt != 0) == 0) return;   // all-zero: exit

    for (int r = 0; r < 256; r++) {
        const int cnt = s_cnt_arr[r];
        if (cnt == 0) continue;
        const int b = b0 + r;

        if (tid < cnt) {
            s_val[tid] = g_val[b * NALIVE + tid];
            s_idx[tid] = g_idx[b * NALIVE + tid];
        }
        __syncthreads();

        float* __restrict__ orow = out + (size_t)b * VOCAB;
        for (int v = tid; v < VOCAB; v += 256) {
            float acc = 0.f;
            for (int k = 0; k < cnt; k++)
                acc = fmaf(s_val[k], W[(size_t)s_idx[k] * VOCAB + v], acc);
            orow[v] = acc;
        }
        __syncthreads();
    }
}

extern "C" void kernel_launch(void* const* d_in, const int* in_sizes, int n_in,
                              void* d_out, int out_size) {
    const int*   tok = (const int*)  d_in[0];   // [B, S]
    const float* te  = (const float*)d_in[1];   // [V, D]
    const float* pe  = (const float*)d_in[2];   // [S, D]
    const float* q   = (const float*)d_in[3];   // [D]
    const float* pos = (const float*)d_in[4];   // [N, D]
    const float* W   = (const float*)d_in[5];   // [N, V]
    float* out = (float*)d_out;                 // [B, V]

    fused_fill_ctx_kernel<<<BATCH, 320>>>(tok, te, pe, q, pos, out);
    fixup_kernel<<<16, 256>>>(W, out);
}

// round 15
// speedup vs baseline: 1.4713x; 1.4713x over previous
#include <cuda_runtime.h>
#include <cstdint>

#define BATCH   4096
#define SEQ     32
#define DIM     256
#define VOCAB   50257
#define NALIVE  100

// Scratch: compacted nonzero activations per row (empty in practice).
__device__ float g_val[BATCH * NALIVE];
__device__ int   g_idx[BATCH * NALIVE];
__device__ int   g_cnt[BATCH];

__device__ __forceinline__ float warp_sum(float v) {
    #pragma unroll
    for (int off = 16; off > 0; off >>= 1)
        v += __shfl_xor_sync(0xFFFFFFFFu, v, off);
    return v;
}
__device__ __forceinline__ float warp_max(float v) {
    #pragma unroll
    for (int off = 16; off > 0; off >>= 1)
        v = fmaxf(v, __shfl_xor_sync(0xFFFFFFFFu, v, off));
    return v;
}

// Standalone ctx kernel: one block per batch row, smem-staged embeds
// (te/pe read once), full 256-thread phases. ~3.5us/block, ~12-15us total.
__global__ __launch_bounds__(256)
void ctx_kernel(const int*   __restrict__ tok,
                const float* __restrict__ te,
                const float* __restrict__ pe,
                const float* __restrict__ q,
                const float* __restrict__ pos) {
    __shared__ float s_emb[SEQ][DIM];     // 32 KB
    __shared__ float s_q[DIM];
    __shared__ float s_ctx[DIM];
    __shared__ float s_score[SEQ];
    __shared__ float s_w[SEQ];
    __shared__ float s_act[NALIVE];
    __shared__ int   s_tok[SEQ];

    const int b    = blockIdx.x;
    const int tid  = threadIdx.x;          // 0..255
    const int lane = tid & 31;
    const int wid  = tid >> 5;             // 0..7

    s_q[tid] = q[tid];
    if (tid < SEQ) s_tok[tid] = tok[b * SEQ + tid];
    __syncthreads();

    // Phase A: gather embeds into smem. 64 threads/row, 4 rows/pass, 8 passes.
    {
        const int rlane = tid & 63;        // float4 index within a row
        const int rgrp  = tid >> 6;        // 0..3
        #pragma unroll
        for (int p = 0; p < 8; p++) {
            const int s = p * 4 + rgrp;
            const float4 t4 = __ldg((const float4*)(te + (size_t)s_tok[s] * DIM) + rlane);
            const float4 p4 = __ldg((const float4*)(pe + s * DIM) + rlane);
            float4 e;
            e.x = t4.x + p4.x; e.y = t4.y + p4.y;
            e.z = t4.z + p4.z; e.w = t4.w + p4.w;
            *((float4*)&s_emb[s][0] + rlane) = e;
        }
    }
    __syncthreads();

    // Phase B: attention scores (warp w handles s = w, w+8, w+16, w+24)
    #pragma unroll
    for (int s = wid; s < SEQ; s += 8) {
        float p = 0.f;
        #pragma unroll
        for (int i = 0; i < 8; i++) {
            int d = lane + 32 * i;
            p = fmaf(s_emb[s][d], s_q[d], p);
        }
        p = warp_sum(p);
        if (lane == 0) s_score[s] = p * (1.0f / 16.0f);   // / sqrt(256)
    }
    __syncthreads();

    // Phase C: softmax over S=32 (warp 0, one score per lane)
    if (wid == 0) {
        float sc = s_score[lane];
        float m  = warp_max(sc);
        float e  = expf(sc - m);
        float s  = warp_sum(e);
        s_w[lane] = e / s;
    }
    __syncthreads();

    // Phase D: context[d] = sum_s w[s] * embeds[s][d]
    {
        float c = 0.f;
        #pragma unroll
        for (int s = 0; s < SEQ; s++) c = fmaf(s_w[s], s_emb[s][tid], c);
        s_ctx[tid] = c;
    }
    __syncthreads();

    // Phase E: RBF distances to 100 positions (warp w handles j = w, w+8, ...)
    for (int j = wid; j < NALIVE; j += 8) {
        float p = 0.f;
        #pragma unroll
        for (int i = 0; i < 8; i++) {
            int d = lane + 32 * i;
            float df = s_ctx[d] - __ldg(pos + j * DIM + d);
            p = fmaf(df, df, p);
        }
        p = warp_sum(p);
        if (lane == 0) s_act[j] = expf(-2.0f * p);   // exp(-d2 / (2*0.5^2))
    }
    __syncthreads();

    // Phase F: normalize + compact nonzeros (warp 0)
    if (wid == 0) {
        float sum = 0.f;
        for (int j = lane; j < NALIVE; j += 32) sum += s_act[j];
        sum = warp_sum(sum);
        const float denom = sum + 1e-8f;

        int cnt = 0;
        #pragma unroll
        for (int base = 0; base < 128; base += 32) {
            const int j = base + lane;
            float a = 0.f;
            bool nz = false;
            if (j < NALIVE) {
                a  = s_act[j] / denom;
                nz = (a != 0.0f);
            }
            const unsigned m = __ballot_sync(0xFFFFFFFFu, nz);
            const int pre = __popc(m & ((1u << lane) - 1u));
            if (nz) {
                g_val[b * NALIVE + cnt + pre] = a;
                g_idx[b * NALIVE + cnt + pre] = j;
            }
            cnt += __popc(m);
        }
        if (lane == 0) g_cnt[b] = cnt;
    }
}

// Sparse fixup: 16 blocks, each checks 256 rows IN PARALLEL (one load round),
// exits immediately when all counts are zero (the common case, ~4 us).
__global__ __launch_bounds__(256)
void fixup_kernel(const float* __restrict__ W, float* __restrict__ out) {
    __shared__ int   s_cnt_arr[256];
    __shared__ float s_val[NALIVE];
    __shared__ int   s_idx[NALIVE];

    const int tid = threadIdx.x;
    const int b0  = blockIdx.x * 256;

    const int mycnt = g_cnt[b0 + tid];
    s_cnt_arr[tid] = mycnt;
    if (__syncthreads_count(mycnt != 0) == 0) return;   // all-zero: exit

    for (int r = 0; r < 256; r++) {
        const int cnt = s_cnt_arr[r];
        if (cnt == 0) continue;
        const int b = b0 + r;

        if (tid < cnt) {
            s_val[tid] = g_val[b * NALIVE + tid];
            s_idx[tid] = g_idx[b * NALIVE + tid];
        }
        __syncthreads();

        float* __restrict__ orow = out + (size_t)b * VOCAB;
        for (int v = tid; v < VOCAB; v += 256) {
            float acc = 0.f;
            for (int k = 0; k < cnt; k++)
                acc = fmaf(s_val[k], W[(size_t)s_idx[k] * VOCAB + v], acc);
            orow[v] = acc;
        }
        __syncthreads();
    }
}

extern "C" void kernel_launch(void* const* d_in, const int* in_sizes, int n_in,
                              void* d_out, int out_size) {
    const int*   tok = (const int*)  d_in[0];   // [B, S]
    const float* te  = (const float*)d_in[1];   // [V, D]
    const float* pe  = (const float*)d_in[2];   // [S, D]
    const float* q   = (const float*)d_in[3];   // [D]
    const float* pos = (const float*)d_in[4];   // [N, D]
    const float* W   = (const float*)d_in[5];   // [N, V]
    float* out = (float*)d_out;                 // [B, V]

    // 1) ctx/RBF compaction (no dependence on out)
    ctx_kernel<<<BATCH, 256>>>(tok, te, pe, q, pos);
    // 2) zero logits via driver-optimized memset node (0x00 == 0.0f)
    cudaMemsetAsync(d_out, 0, (size_t)out_size * sizeof(float));
    // 3) rewrite the (rare) rows whose activations survived underflow
    fixup_kernel<<<16, 256>>>(W, out);
}

// round 16
// speedup vs baseline: 1.6180x; 1.0997x over previous
#include <cuda_runtime.h>
#include <cstdint>

#define BATCH   4096
#define SEQ     32
#define DIM     256
#define VOCAB   50257
#define NALIVE  100

// Ctx blocks occupy bids [0, 4096) — dispatched in wave 1, hidden behind the
// store-queue ramp. Fill blocks occupy bids [4096, 20480): every later wave
// and the kernel tail are a pure write stream.
#define NCTX    4096
#define NZB     16384
#define NBTOT   20480
#define TOTAL4  51463168  // BATCH*VOCAB/4

// Scratch: compacted nonzero activations per row (empty in practice).
__device__ float g_val[BATCH * NALIVE];
__device__ int   g_idx[BATCH * NALIVE];
__device__ int   g_cnt[BATCH];

__device__ __forceinline__ float warp_sum(float v) {
    #pragma unroll
    for (int off = 16; off > 0; off >>= 1)
        v += __shfl_xor_sync(0xFFFFFFFFu, v, off);
    return v;
}
__device__ __forceinline__ float warp_max(float v) {
    #pragma unroll
    for (int off = 16; off > 0; off >>= 1)
        v = fmaxf(v, __shfl_xor_sync(0xFFFFFFFFu, v, off));
    return v;
}

// Low-smem + low-reg: __launch_bounds__(256, 8) keeps regs<=32 so fill blocks
// get 8 blocks/SM. Ctx role reads te twice from L2 (hot after first touch).
__global__ __launch_bounds__(256, 8)
void fused_fill_ctx_kernel(const int*   __restrict__ tok,
                           const float* __restrict__ te,
                           const float* __restrict__ pe,
                           const float* __restrict__ q,
                           const float* __restrict__ pos,
                           float*       __restrict__ out) {
    const int bid = blockIdx.x;
    const int tid = threadIdx.x;            // 0..255

    if (bid >= NCTX) {
        // -------- zero-fill role (bids 4096..20479, every wave after 1) ----
        const int zid = bid - NCTX;                      // 0..16383
        const float4 z = make_float4(0.f, 0.f, 0.f, 0.f);
        float4* __restrict__ o4 = (float4*)out;
        const long stride = (long)NZB * 256;
        for (long i = (long)zid * 256 + tid; i < (long)TOTAL4; i += stride)
            __stcs(o4 + i, z);
        return;
    }

    // -------- ctx role (bids 0..4095, dispatched during store ramp) --------
    const int b = bid;

    __shared__ float s_q[DIM];        // 1 KB
    __shared__ float s_ctx[DIM];      // 1 KB
    __shared__ float s_score[SEQ];
    __shared__ float s_w[SEQ];
    __shared__ float s_act[NALIVE];
    __shared__ int   s_tok[SEQ];

    const int lane = tid & 31;
    const int wid  = tid >> 5;             // 0..7

    s_q[tid] = q[tid];
    if (tid < SEQ) s_tok[tid] = tok[b * SEQ + tid];
    __syncthreads();

    // Phase B: attention scores, embeds read from global/L2 on the fly.
    // Warp w handles s = w, w+8, w+16, w+24.
    #pragma unroll
    for (int s = wid; s < SEQ; s += 8) {
        const float* __restrict__ trow = te + (size_t)s_tok[s] * DIM;
        const float* __restrict__ prow = pe + s * DIM;
        float p = 0.f;
        #pragma unroll
        for (int i = 0; i < 8; i++) {
            int d = lane + 32 * i;
            p = fmaf(__ldg(trow + d) + __ldg(prow + d), s_q[d], p);
        }
        p = warp_sum(p);
        if (lane == 0) s_score[s] = p * (1.0f / 16.0f);   // / sqrt(256)
    }
    __syncthreads();

    // Phase C: softmax over S=32 (warp 0, one score per lane)
    if (wid == 0) {
        float sc = s_score[lane];
        float m  = warp_max(sc);
        float e  = expf(sc - m);
        float s  = warp_sum(e);
        s_w[lane] = e / s;
    }
    __syncthreads();

    // Phase D: context[d] = sum_s w[s] * (te[tok[s]][d] + pe[s][d])  (L2-warm)
    {
        const int d = tid;
        float c = 0.f;
        #pragma unroll
        for (int s = 0; s < SEQ; s++) {
            float e = __ldg(te + (size_t)s_tok[s] * DIM + d) + __ldg(pe + s * DIM + d);
            c = fmaf(s_w[s], e, c);
        }
        s_ctx[d] = c;
    }
    __syncthreads();

    // Phase E: RBF distances to 100 positions (warp w handles j = w, w+8, ...)
    for (int j = wid; j < NALIVE; j += 8) {
        float p = 0.f;
        #pragma unroll
        for (int i = 0; i < 8; i++) {
            int d = lane + 32 * i;
            float df = s_ctx[d] - __ldg(pos + j * DIM + d);
            p = fmaf(df, df, p);
        }
        p = warp_sum(p);
        if (lane == 0) s_act[j] = expf(-2.0f * p);   // exp(-d2 / (2*0.5^2))
    }
    __syncthreads();

    // Phase F: normalize + compact nonzeros (warp 0)
    if (wid == 0) {
        float sum = 0.f;
        for (int j = lane; j < NALIVE; j += 32) sum += s_act[j];
        sum = warp_sum(sum);
        const float denom = sum + 1e-8f;

        int cnt = 0;
        #pragma unroll
        for (int base = 0; base < 128; base += 32) {
            const int j = base + lane;
            float a = 0.f;
            bool nz = false;
            if (j < NALIVE) {
                a  = s_act[j] / denom;
                nz = (a != 0.0f);
            }
            const unsigned m = __ballot_sync(0xFFFFFFFFu, nz);
            const int pre = __popc(m & ((1u << lane) - 1u));
            if (nz) {
                g_val[b * NALIVE + cnt + pre] = a;
                g_idx[b * NALIVE + cnt + pre] = j;
            }
            cnt += __popc(m);
        }
        if (lane == 0) g_cnt[b] = cnt;
    }
}

// Sparse fixup: 16 blocks, each checks 256 rows IN PARALLEL (one load round),
// exits immediately when all counts are zero (the common case, ~4 us).
__global__ __launch_bounds__(256)
void fixup_kernel(const float* __restrict__ W, float* __restrict__ out) {
    __shared__ int   s_cnt_arr[256];
    __shared__ float s_val[NALIVE];
    __shared__ int   s_idx[NALIVE];

    const int tid = threadIdx.x;
    const int b0  = blockIdx.x * 256;

    const int mycnt = g_cnt[b0 + tid];
    s_cnt_arr[tid] = mycnt;
    if (__syncthreads_count(mycnt != 0) == 0) return;   // all-zero: exit

    for (int r = 0; r < 256; r++) {
        const int cnt = s_cnt_arr[r];
        if (cnt == 0) continue;
        const int b = b0 + r;

        if (tid < cnt) {
            s_val[tid] = g_val[b * NALIVE + tid];
            s_idx[tid] = g_idx[b * NALIVE + tid];
        }
        __syncthreads();

        float* __restrict__ orow = out + (size_t)b * VOCAB;
        for (int v = tid; v < VOCAB; v += 256) {
            float acc = 0.f;
            for (int k = 0; k < cnt; k++)
                acc = fmaf(s_val[k], W[(size_t)s_idx[k] * VOCAB + v], acc);
            orow[v] = acc;
        }
        __syncthreads();
    }
}

extern "C" void kernel_launch(void* const* d_in, const int* in_sizes, int n_in,
                              void* d_out, int out_size) {
    const int*   tok = (const int*)  d_in[0];   // [B, S]
    const float* te  = (const float*)d_in[1];   // [V, D]
    const float* pe  = (const float*)d_in[2];   // [S, D]
    const float* q   = (const float*)d_in[3];   // [D]
    const float* pos = (const float*)d_in[4];   // [N, D]
    const float* W   = (const float*)d_in[5];   // [N, V]
    float* out = (float*)d_out;                 // [B, V]

    fused_fill_ctx_kernel<<<NBTOT, 256>>>(tok, te, pe, q, pos, out);
    fixup_kernel<<<16, 256>>>(W, out);
}